// round 4
// baseline (speedup 1.0000x reference)
#include <cuda_runtime.h>

// Problem constants
#define N_ROWS   1344              // B*C = 64*21
#define R_WIN    32                // windows per row (L/MAX_PL = 1024/32)
#define DM       512               // D_MODEL
#define TGT      4                 // MAX_PL/MIN_PL
#define PE_LEN   128               // R_WIN * TGT
#define MAIN_OUT ((long long)N_ROWS * PE_LEN * DM)  // 88080384
#define EMB_BLOCKS (N_ROWS * 2)    // 2688

// ---------------------------------------------------------------------------
// Single fused kernel:
//   block b < 2688: n = b>>1, covers dims [ (b&1)*256, +256 ).
//     phase 1: cooperative x-row load + weight staging
//     phase 2: in-block classifier (thread = (window w = tid>>3, h-octet tid&7),
//              shfl_xor reduce over 8 lanes) -> s_pred[32]
//     phase 3: per-window embedding + repeat + PE recurrence + store
//   block b >= 2688: tail fill (reference returns (x_patch, C=21)).
//
// Weights: we2 (32f, hot path) in registers; we0/we1 in smem with row pads
// 9 and 17 (coprime with 32 -> conflict-free LDS). This caps regs <= 83 so
// __launch_bounds__(256,3) gives 3 CTAs/SM (24 warps).
// PE: in-register rotation recurrence, zero loads.
// ---------------------------------------------------------------------------
__global__ void __launch_bounds__(256, 3)
fused_kernel(const float* __restrict__ x,
             const float* __restrict__ w1,
             const float* __restrict__ b1,
             const float* __restrict__ w2,
             const float* __restrict__ b2,
             const float* __restrict__ we0,   // [512][8]
             const float* __restrict__ we1,   // [512][16]
             const float* __restrict__ we2,   // [512][32]
             float* __restrict__ out,
             long long tail_start, long long total) {
    if (blockIdx.x >= EMB_BLOCKS) {
        long long i = tail_start + (long long)(blockIdx.x - EMB_BLOCKS) * 256 + threadIdx.x;
        if (i < total) out[i] = 21.0f;
        return;
    }

    __shared__ __align__(16) float s_x[R_WIN * 32];   // 4 KB
    __shared__ float s_w0[256 * 9];                    // 9 KB  (pad 8->9)
    __shared__ float s_w1[256 * 17];                   // 17 KB (pad 16->17)
    __shared__ unsigned char s_pred[R_WIN];

    const int tid  = threadIdx.x;
    const int n    = blockIdx.x >> 1;
    const int dblk = (blockIdx.x & 1) << 8;
    const int d    = dblk + tid;

    // --- phase 1: stage x row + weights ---
    ((float4*)s_x)[tid] = ((const float4*)(x + (size_t)n * 1024))[tid];
    {
        const float4* p0 = (const float4*)(we0 + d * 8);
        float4 a = p0[0], b = p0[1];
        float* r = s_w0 + tid * 9;
        r[0] = a.x; r[1] = a.y; r[2] = a.z; r[3] = a.w;
        r[4] = b.x; r[5] = b.y; r[6] = b.z; r[7] = b.w;
    }
    {
        const float4* p1 = (const float4*)(we1 + d * 16);
        float* r = s_w1 + tid * 17;
#pragma unroll
        for (int i = 0; i < 4; i++) {
            float4 a = p1[i];
            r[4*i] = a.x; r[4*i+1] = a.y; r[4*i+2] = a.z; r[4*i+3] = a.w;
        }
    }
    float4 r2[8];
    {
        const float4* p2 = (const float4*)(we2 + d * 32);
#pragma unroll
        for (int i = 0; i < 8; i++) r2[i] = p2[i];
    }

    // PE recurrence setup.
    const float kLn = -9.21034037197618f / (float)DM;   // -ln(10000)/512
    float delta = expf((float)(d & ~1) * kLn);
    float sd, cd;
    sincosf(delta, &sd, &cd);
    float s = 0.0f, c = 1.0f;
    const bool use_cos = (d & 1);

    __syncthreads();

    // --- phase 2: classifier (both half-blocks compute redundantly; cheap) ---
    {
        int w = tid >> 3;       // window 0..31
        int p = tid & 7;        // h-octet 0..7
        const float4* xw = (const float4*)(s_x + w * 32);
        float4 xv[8];
#pragma unroll
        for (int i = 0; i < 8; i++) xv[i] = xw[i];

        float l0 = 0.f, l1 = 0.f, l2 = 0.f;
#pragma unroll
        for (int j = 0; j < 8; j++) {
            int h = p * 8 + j;
            const float4* wr = (const float4*)(w1 + h * 32);
            float a0 = 0.f, a1 = 0.f, a2 = 0.f, a3 = 0.f;
#pragma unroll
            for (int i = 0; i < 8; i++) {
                float4 wv = __ldg(&wr[i]);
                a0 = fmaf(wv.x, xv[i].x, a0);
                a1 = fmaf(wv.y, xv[i].y, a1);
                a2 = fmaf(wv.z, xv[i].z, a2);
                a3 = fmaf(wv.w, xv[i].w, a3);
            }
            float hv = b1[h] + ((a0 + a1) + (a2 + a3));
            hv = fmaxf(hv, 0.0f);
            l0 = fmaf(w2[h], hv, l0);
            l1 = fmaf(w2[64 + h], hv, l1);
            l2 = fmaf(w2[128 + h], hv, l2);
        }
#pragma unroll
        for (int m = 1; m < 8; m <<= 1) {
            l0 += __shfl_xor_sync(0xffffffffu, l0, m);
            l1 += __shfl_xor_sync(0xffffffffu, l1, m);
            l2 += __shfl_xor_sync(0xffffffffu, l2, m);
        }
        if (p == 0) {
            l0 += b2[0]; l1 += b2[1]; l2 += b2[2];
            int pr = 0;
            float mm = l0;
            if (l1 > mm) { mm = l1; pr = 1; }   // strict > = first-max (jnp.argmax)
            if (l2 > mm) { mm = l2; pr = 2; }
            s_pred[w] = (unsigned char)pr;
        }
    }
    __syncthreads();

    // --- phase 3: embedding + PE + store ---
    float* outn = out + (size_t)n * (PE_LEN * DM);
    const float* w0r = s_w0 + tid * 9;
    const float* w1r = s_w1 + tid * 17;

#pragma unroll 1
    for (int w = 0; w < R_WIN; w++) {
        int pred = s_pred[w];
        const float4* xq = (const float4*)(s_x + w * 32);

        float v0, v1, v2, v3;
        if (pred == 2) {
            // 1 patch of 32 -> replicated 4x
            float c0 = 0.f, c1 = 0.f, c2 = 0.f, c3 = 0.f;
#pragma unroll
            for (int i = 0; i < 8; i += 4) {
                float4 x0 = xq[i], x1 = xq[i+1], x2 = xq[i+2], x3 = xq[i+3];
                c0 = fmaf(r2[i].x,   x0.x, c0);
                c0 = fmaf(r2[i].y,   x0.y, c0);
                c0 = fmaf(r2[i].z,   x0.z, c0);
                c0 = fmaf(r2[i].w,   x0.w, c0);
                c1 = fmaf(r2[i+1].x, x1.x, c1);
                c1 = fmaf(r2[i+1].y, x1.y, c1);
                c1 = fmaf(r2[i+1].z, x1.z, c1);
                c1 = fmaf(r2[i+1].w, x1.w, c1);
                c2 = fmaf(r2[i+2].x, x2.x, c2);
                c2 = fmaf(r2[i+2].y, x2.y, c2);
                c2 = fmaf(r2[i+2].z, x2.z, c2);
                c2 = fmaf(r2[i+2].w, x2.w, c2);
                c3 = fmaf(r2[i+3].x, x3.x, c3);
                c3 = fmaf(r2[i+3].y, x3.y, c3);
                c3 = fmaf(r2[i+3].z, x3.z, c3);
                c3 = fmaf(r2[i+3].w, x3.w, c3);
            }
            float cc = (c0 + c1) + (c2 + c3);
            v0 = cc; v1 = cc; v2 = cc; v3 = cc;
        } else if (pred == 1) {
            // 2 patches of 16; repeat idx = [0,0,0,1]
            float q0 = w1r[0],  q1 = w1r[1],  q2 = w1r[2],  q3 = w1r[3];
            float q4 = w1r[4],  q5 = w1r[5],  q6 = w1r[6],  q7 = w1r[7];
            float q8 = w1r[8],  q9 = w1r[9],  qa = w1r[10], qb = w1r[11];
            float qc = w1r[12], qd = w1r[13], qe = w1r[14], qf = w1r[15];
            float a = 0.f, b = 0.f;
#pragma unroll
            for (int half = 0; half < 2; half++) {
                float acc = 0.f;
                float4 x0 = xq[half*4+0], x1 = xq[half*4+1];
                float4 x2 = xq[half*4+2], x3 = xq[half*4+3];
                acc = fmaf(q0, x0.x, acc); acc = fmaf(q1, x0.y, acc);
                acc = fmaf(q2, x0.z, acc); acc = fmaf(q3, x0.w, acc);
                acc = fmaf(q4, x1.x, acc); acc = fmaf(q5, x1.y, acc);
                acc = fmaf(q6, x1.z, acc); acc = fmaf(q7, x1.w, acc);
                acc = fmaf(q8, x2.x, acc); acc = fmaf(q9, x2.y, acc);
                acc = fmaf(qa, x2.z, acc); acc = fmaf(qb, x2.w, acc);
                acc = fmaf(qc, x3.x, acc); acc = fmaf(qd, x3.y, acc);
                acc = fmaf(qe, x3.z, acc); acc = fmaf(qf, x3.w, acc);
                if (half == 0) a = acc; else b = acc;
            }
            v0 = a; v1 = a; v2 = a; v3 = b;
        } else {
            // 4 patches of 8; repeat idx = [0,1,2,3]
            float q0 = w0r[0], q1 = w0r[1], q2 = w0r[2], q3 = w0r[3];
            float q4 = w0r[4], q5 = w0r[5], q6 = w0r[6], q7 = w0r[7];
            float acc[4];
#pragma unroll
            for (int k = 0; k < 4; k++) {
                float4 x0 = xq[k*2], x1 = xq[k*2+1];
                float t = q0 * x0.x;
                t = fmaf(q1, x0.y, t);
                t = fmaf(q2, x0.z, t);
                t = fmaf(q3, x0.w, t);
                t = fmaf(q4, x1.x, t);
                t = fmaf(q5, x1.y, t);
                t = fmaf(q6, x1.z, t);
                t = fmaf(q7, x1.w, t);
                acc[k] = t;
            }
            v0 = acc[0]; v1 = acc[1]; v2 = acc[2]; v3 = acc[3];
        }

        // PE via rotation recurrence — 4 positions, zero loads.
        float p0 = use_cos ? c : s;
        { float ns = fmaf(s, cd, c * sd); float nc = fmaf(c, cd, -s * sd); s = ns; c = nc; }
        float p1 = use_cos ? c : s;
        { float ns = fmaf(s, cd, c * sd); float nc = fmaf(c, cd, -s * sd); s = ns; c = nc; }
        float p2 = use_cos ? c : s;
        { float ns = fmaf(s, cd, c * sd); float nc = fmaf(c, cd, -s * sd); s = ns; c = nc; }
        float p3 = use_cos ? c : s;
        { float ns = fmaf(s, cd, c * sd); float nc = fmaf(c, cd, -s * sd); s = ns; c = nc; }

        float* o = outn + (size_t)w * (TGT * DM) + d;
        o[0 * DM] = v0 + p0;
        o[1 * DM] = v1 + p1;
        o[2 * DM] = v2 + p2;
        o[3 * DM] = v3 + p3;
    }
}

extern "C" void kernel_launch(void* const* d_in, const int* in_sizes, int n_in,
                              void* d_out, int out_size) {
    const float* x   = (const float*)d_in[0];
    const float* w1  = (const float*)d_in[1];
    const float* b1  = (const float*)d_in[2];
    const float* w2  = (const float*)d_in[3];
    const float* b2  = (const float*)d_in[4];
    const float* we0 = (const float*)d_in[5];
    const float* we1 = (const float*)d_in[6];
    const float* we2 = (const float*)d_in[7];
    float* out = (float*)d_out;

    long long total = (long long)out_size;
    long long tail  = (total > MAIN_OUT) ? (total - MAIN_OUT) : 0;
    int tail_blocks = (int)((tail + 255) / 256);

    fused_kernel<<<EMB_BLOCKS + tail_blocks, 256>>>(
        x, w1, b1, w2, b2, we0, we1, we2, out, MAIN_OUT, total);
}

// round 5
// speedup vs baseline: 1.0404x; 1.0404x over previous
#include <cuda_runtime.h>

// Problem constants
#define N_ROWS   1344              // B*C = 64*21
#define R_WIN    32                // windows per row (L/MAX_PL = 1024/32)
#define DM       512               // D_MODEL
#define TGT      4                 // MAX_PL/MIN_PL
#define PE_LEN   128               // R_WIN * TGT
#define MAIN_OUT ((long long)N_ROWS * PE_LEN * DM)  // 88080384
#define EMB_BLOCKS (N_ROWS * 2)    // 2688

// ---------------------------------------------------------------------------
// Single fused kernel. Block b < 2688: n = b>>1, dims [(b&1)*256, +256).
//   phase 1: stage x row (4KB smem) + r0/r2 weights into REGISTERS,
//            r1 (we1) into padded smem (stride 17, conflict-free).
//   phase 2: in-block classifier (thread = (window tid>>3, h-octet tid&7),
//            shfl_xor reduce over 8 lanes) -> s_pred[32].
//   phase 3: per-window embedding + repeat + PE rotation recurrence + store.
// Weights for pred 0/2 never touch smem in the loop (R4 lesson: the smem
// crossbar saturates if they do). pred==1 pays 16 scalar conflict-free LDS
// on ~1/3 of windows only.
// ---------------------------------------------------------------------------
__global__ void __launch_bounds__(256, 3)
fused_kernel(const float* __restrict__ x,
             const float* __restrict__ w1,
             const float* __restrict__ b1,
             const float* __restrict__ w2,
             const float* __restrict__ b2,
             const float* __restrict__ we0,   // [512][8]
             const float* __restrict__ we1,   // [512][16]
             const float* __restrict__ we2,   // [512][32]
             float* __restrict__ out,
             long long tail_start, long long total) {
    if (blockIdx.x >= EMB_BLOCKS) {
        long long i = tail_start + (long long)(blockIdx.x - EMB_BLOCKS) * 256 + threadIdx.x;
        if (i < total) out[i] = 21.0f;
        return;
    }

    __shared__ __align__(16) float s_x[R_WIN * 32];   // 4 KB
    __shared__ float s_w1t[256 * 17];                  // 17 KB (pad 16->17)
    __shared__ unsigned char s_pred[R_WIN];

    const int tid  = threadIdx.x;
    const int n    = blockIdx.x >> 1;
    const int dblk = (blockIdx.x & 1) << 8;
    const int d    = dblk + tid;

    // --- phase 1: stage x row + weights ---
    ((float4*)s_x)[tid] = ((const float4*)(x + (size_t)n * 1024))[tid];

    // we1 row -> padded smem (only touched on pred==1 windows).
    {
        const float4* p1 = (const float4*)(we1 + d * 16);
        float* r = s_w1t + tid * 17;
#pragma unroll
        for (int i = 0; i < 4; i++) {
            float4 a = p1[i];
            r[4*i] = a.x; r[4*i+1] = a.y; r[4*i+2] = a.z; r[4*i+3] = a.w;
        }
    }
    // we0 row (8 floats) and we2 row (32 floats) in registers.
    float4 r0[2], r2[8];
    {
        const float4* p0 = (const float4*)(we0 + d * 8);
        r0[0] = p0[0]; r0[1] = p0[1];
        const float4* p2 = (const float4*)(we2 + d * 32);
#pragma unroll
        for (int i = 0; i < 8; i++) r2[i] = p2[i];
    }

    // PE rotation recurrence setup.
    const float kLn = -9.21034037197618f / (float)DM;   // -ln(10000)/512
    float delta = expf((float)(d & ~1) * kLn);
    float sd, cd;
    sincosf(delta, &sd, &cd);
    float s = 0.0f, c = 1.0f;
    const bool use_cos = (d & 1);

    __syncthreads();

    // --- phase 2: classifier (redundant across the two d-half blocks; cheap) ---
    {
        int w = tid >> 3;       // window 0..31
        int p = tid & 7;        // h-octet 0..7
        const float4* xw = (const float4*)(s_x + w * 32);

        float l0 = 0.f, l1 = 0.f, l2 = 0.f;
#pragma unroll
        for (int j = 0; j < 8; j++) {
            int h = p * 8 + j;
            const float4* wr = (const float4*)(w1 + h * 32);
            float a0 = 0.f, a1 = 0.f, a2 = 0.f, a3 = 0.f;
#pragma unroll
            for (int i = 0; i < 8; i++) {
                float4 wv = __ldg(&wr[i]);
                float4 xv = xw[i];
                a0 = fmaf(wv.x, xv.x, a0);
                a1 = fmaf(wv.y, xv.y, a1);
                a2 = fmaf(wv.z, xv.z, a2);
                a3 = fmaf(wv.w, xv.w, a3);
            }
            float hv = b1[h] + ((a0 + a1) + (a2 + a3));
            hv = fmaxf(hv, 0.0f);
            l0 = fmaf(w2[h], hv, l0);
            l1 = fmaf(w2[64 + h], hv, l1);
            l2 = fmaf(w2[128 + h], hv, l2);
        }
#pragma unroll
        for (int m = 1; m < 8; m <<= 1) {
            l0 += __shfl_xor_sync(0xffffffffu, l0, m);
            l1 += __shfl_xor_sync(0xffffffffu, l1, m);
            l2 += __shfl_xor_sync(0xffffffffu, l2, m);
        }
        if (p == 0) {
            l0 += b2[0]; l1 += b2[1]; l2 += b2[2];
            int pr = 0;
            float mm = l0;
            if (l1 > mm) { mm = l1; pr = 1; }   // strict > = first-max (jnp.argmax)
            if (l2 > mm) { mm = l2; pr = 2; }
            s_pred[w] = (unsigned char)pr;
        }
    }
    __syncthreads();

    // --- phase 3: embedding + PE + store ---
    float* outn = out + (size_t)n * (PE_LEN * DM);
    const float* w1r = s_w1t + tid * 17;

#pragma unroll 1
    for (int w = 0; w < R_WIN; w++) {
        int pred = s_pred[w];
        const float4* xq = (const float4*)(s_x + w * 32);

        float v0, v1, v2, v3;
        if (pred == 2) {
            // 1 patch of 32 -> replicated 4x (weights in registers)
            float c0 = 0.f, c1 = 0.f, c2 = 0.f, c3 = 0.f;
#pragma unroll
            for (int i = 0; i < 8; i += 4) {
                float4 x0 = xq[i], x1 = xq[i+1], x2 = xq[i+2], x3 = xq[i+3];
                c0 = fmaf(r2[i].x,   x0.x, c0);
                c0 = fmaf(r2[i].y,   x0.y, c0);
                c0 = fmaf(r2[i].z,   x0.z, c0);
                c0 = fmaf(r2[i].w,   x0.w, c0);
                c1 = fmaf(r2[i+1].x, x1.x, c1);
                c1 = fmaf(r2[i+1].y, x1.y, c1);
                c1 = fmaf(r2[i+1].z, x1.z, c1);
                c1 = fmaf(r2[i+1].w, x1.w, c1);
                c2 = fmaf(r2[i+2].x, x2.x, c2);
                c2 = fmaf(r2[i+2].y, x2.y, c2);
                c2 = fmaf(r2[i+2].z, x2.z, c2);
                c2 = fmaf(r2[i+2].w, x2.w, c2);
                c3 = fmaf(r2[i+3].x, x3.x, c3);
                c3 = fmaf(r2[i+3].y, x3.y, c3);
                c3 = fmaf(r2[i+3].z, x3.z, c3);
                c3 = fmaf(r2[i+3].w, x3.w, c3);
            }
            float cc = (c0 + c1) + (c2 + c3);
            v0 = cc; v1 = cc; v2 = cc; v3 = cc;
        } else if (pred == 1) {
            // 2 patches of 16; repeat idx = [0,0,0,1] (weights from padded smem)
            float a = 0.f, b = 0.f;
#pragma unroll
            for (int i = 0; i < 4; i++) {
                float4 xv = xq[i];
                a = fmaf(w1r[4*i+0], xv.x, a);
                a = fmaf(w1r[4*i+1], xv.y, a);
                a = fmaf(w1r[4*i+2], xv.z, a);
                a = fmaf(w1r[4*i+3], xv.w, a);
            }
#pragma unroll
            for (int i = 0; i < 4; i++) {
                float4 xv = xq[4 + i];
                b = fmaf(w1r[4*i+0], xv.x, b);
                b = fmaf(w1r[4*i+1], xv.y, b);
                b = fmaf(w1r[4*i+2], xv.z, b);
                b = fmaf(w1r[4*i+3], xv.w, b);
            }
            v0 = a; v1 = a; v2 = a; v3 = b;
        } else {
            // 4 patches of 8; repeat idx = [0,1,2,3] (weights in registers)
            float acc[4];
#pragma unroll
            for (int k = 0; k < 4; k++) {
                float4 x0 = xq[k*2], x1 = xq[k*2+1];
                float t = r0[0].x * x0.x;
                t = fmaf(r0[0].y, x0.y, t);
                t = fmaf(r0[0].z, x0.z, t);
                t = fmaf(r0[0].w, x0.w, t);
                t = fmaf(r0[1].x, x1.x, t);
                t = fmaf(r0[1].y, x1.y, t);
                t = fmaf(r0[1].z, x1.z, t);
                t = fmaf(r0[1].w, x1.w, t);
                acc[k] = t;
            }
            v0 = acc[0]; v1 = acc[1]; v2 = acc[2]; v3 = acc[3];
        }

        // PE via rotation recurrence — 4 positions, zero loads.
        float p0 = use_cos ? c : s;
        { float ns = fmaf(s, cd, c * sd); float nc = fmaf(c, cd, -s * sd); s = ns; c = nc; }
        float p1 = use_cos ? c : s;
        { float ns = fmaf(s, cd, c * sd); float nc = fmaf(c, cd, -s * sd); s = ns; c = nc; }
        float p2 = use_cos ? c : s;
        { float ns = fmaf(s, cd, c * sd); float nc = fmaf(c, cd, -s * sd); s = ns; c = nc; }
        float p3 = use_cos ? c : s;
        { float ns = fmaf(s, cd, c * sd); float nc = fmaf(c, cd, -s * sd); s = ns; c = nc; }

        float* o = outn + (size_t)w * (TGT * DM) + d;
        o[0 * DM] = v0 + p0;
        o[1 * DM] = v1 + p1;
        o[2 * DM] = v2 + p2;
        o[3 * DM] = v3 + p3;
    }
}

extern "C" void kernel_launch(void* const* d_in, const int* in_sizes, int n_in,
                              void* d_out, int out_size) {
    const float* x   = (const float*)d_in[0];
    const float* w1  = (const float*)d_in[1];
    const float* b1  = (const float*)d_in[2];
    const float* w2  = (const float*)d_in[3];
    const float* b2  = (const float*)d_in[4];
    const float* we0 = (const float*)d_in[5];
    const float* we1 = (const float*)d_in[6];
    const float* we2 = (const float*)d_in[7];
    float* out = (float*)d_out;

    long long total = (long long)out_size;
    long long tail  = (total > MAIN_OUT) ? (total - MAIN_OUT) : 0;
    int tail_blocks = (int)((tail + 255) / 256);

    fused_kernel<<<EMB_BLOCKS + tail_blocks, 256>>>(
        x, w1, b1, w2, b2, we0, we1, we2, out, MAIN_OUT, total);
}